// round 4
// baseline (speedup 1.0000x reference)
#include <cuda_runtime.h>

// score[e] = sum_d h[src[e], d] * h[dst[e], d]
// h: [100000, 32] fp32 ; src/dst: int32 [E] ; out: fp32 [E]
//
// 8 lanes per group, 4 edges per group:
//  - int4 broadcast index loads (4 src + 4 dst idx per group)
//  - 8 independent float4 gathers (MLP=8; each group touches exactly one
//    128B line per gathered row -> minimal L1tex wavefronts)
//  - value-halving shuffle reduction: 4 shuffles total for 4 edge-sums
//    (vs 12 for naive 3-level x 4-value butterfly)
//  - results land on lanes 0,2,4,6 of each group -> dense coalesced store

static constexpr int D = 32;
static constexpr int EDGES_PER_GROUP = 4;
static constexpr unsigned FULL = 0xFFFFFFFFu;

__device__ __forceinline__ float dot4(float4 a, float4 b) {
    return a.x * b.x + a.y * b.y + a.z * b.z + a.w * b.w;
}

__device__ __forceinline__ float red8(float p) {
    p += __shfl_xor_sync(FULL, p, 1);
    p += __shfl_xor_sync(FULL, p, 2);
    p += __shfl_xor_sync(FULL, p, 4);
    return p;
}

__global__ __launch_bounds__(256) void edge_dot_kernel(
    const float* __restrict__ h,
    const int* __restrict__ src,
    const int* __restrict__ dst,
    float* __restrict__ out,
    int E)
{
    int gid = blockIdx.x * blockDim.x + threadIdx.x;
    int g = gid >> 3;                 // 8-lane group index
    int i = gid & 7;                  // lane within group
    long long e0 = (long long)g * EDGES_PER_GROUP;
    if (e0 >= E) return;

    if (e0 + EDGES_PER_GROUP <= E) {
        int4 s4 = *reinterpret_cast<const int4*>(src + e0);
        int4 d4 = *reinterpret_cast<const int4*>(dst + e0);

        // 8 independent gathers in flight
        float4 a0 = reinterpret_cast<const float4*>(h + (long long)s4.x * D)[i];
        float4 b0 = reinterpret_cast<const float4*>(h + (long long)d4.x * D)[i];
        float4 a1 = reinterpret_cast<const float4*>(h + (long long)s4.y * D)[i];
        float4 b1 = reinterpret_cast<const float4*>(h + (long long)d4.y * D)[i];
        float4 a2 = reinterpret_cast<const float4*>(h + (long long)s4.z * D)[i];
        float4 b2 = reinterpret_cast<const float4*>(h + (long long)d4.z * D)[i];
        float4 a3 = reinterpret_cast<const float4*>(h + (long long)s4.w * D)[i];
        float4 b3 = reinterpret_cast<const float4*>(h + (long long)d4.w * D)[i];

        float p0 = dot4(a0, b0);
        float p1 = dot4(a1, b1);
        float p2 = dot4(a2, b2);
        float p3 = dot4(a3, b3);

        // --- value-halving reduction over the 8-lane group (4 shuffles) ---
        bool hi4 = (i & 4) != 0;
        // level xor-4: 4 values -> 2. low lanes keep (v0,v1), high keep (v2,v3)
        float ua = hi4 ? p0 : p2;
        float va = __shfl_xor_sync(FULL, ua, 4);
        float ub = hi4 ? p1 : p3;
        float vb = __shfl_xor_sync(FULL, ub, 4);
        float q0 = (hi4 ? p2 : p0) + va;
        float q1 = (hi4 ? p3 : p1) + vb;

        // level xor-2: 2 values -> 1
        bool hi2 = (i & 2) != 0;
        float uc = hi2 ? q0 : q1;
        float vc = __shfl_xor_sync(FULL, uc, 2);
        float r = (hi2 ? q1 : q0) + vc;

        // level xor-1: final fold
        r += __shfl_xor_sync(FULL, r, 1);

        // lane 2k holds the full sum for edge e0+k (k = i>>1)
        if ((i & 1) == 0) out[e0 + (i >> 1)] = r;
    } else {
        // remainder (E not divisible by 4)
        for (long long e = e0; e < E; ++e) {
            int s = src[e];
            int d = dst[e];
            float4 a = reinterpret_cast<const float4*>(h + (long long)s * D)[i];
            float4 b = reinterpret_cast<const float4*>(h + (long long)d * D)[i];
            float p = red8(dot4(a, b));
            if (i == 0) out[e] = p;
        }
    }
}

extern "C" void kernel_launch(void* const* d_in, const int* in_sizes, int n_in,
                              void* d_out, int out_size)
{
    const float* h   = (const float*)d_in[0];
    const int*   src = (const int*)d_in[1];
    const int*   dst = (const int*)d_in[2];
    float*       out = (float*)d_out;

    int E = in_sizes[1];
    long long groups = ((long long)E + EDGES_PER_GROUP - 1) / EDGES_PER_GROUP;
    long long total_threads = groups * 8;
    int block = 256;
    int grid = (int)((total_threads + block - 1) / block);

    edge_dot_kernel<<<grid, block>>>(h, src, dst, out, E);
}

// round 5
// speedup vs baseline: 1.0132x; 1.0132x over previous
#include <cuda_runtime.h>

// score[e] = sum_d h[src[e], d] * h[dst[e], d]
// h: [100000, 32] fp32 ; src/dst: int32 [E] ; out: fp32 [E]
//
// 8 lanes per group, 4 edges per group:
//  - int4 broadcast index loads (4 src + 4 dst idx per group)
//  - 8 independent float4 gathers (MLP=8; each group touches exactly one
//    128B line per gathered row -> 2 L1tex wavefronts/edge, the floor)
//  - value-halving shuffle reduction: 4 shuffles for 4 edge-sums
//  - results land on lanes 0,2,4,6 -> dense coalesced store
//  - __launch_bounds__(256, 8) forces regs<=32 so occupancy returns to 100%
//    of the 2048-thread cap (R4's 40 regs cost 20pts of occupancy for zero
//    net gain)

static constexpr int D = 32;
static constexpr int EDGES_PER_GROUP = 4;
static constexpr unsigned FULL = 0xFFFFFFFFu;

__device__ __forceinline__ float dot4(float4 a, float4 b) {
    return a.x * b.x + a.y * b.y + a.z * b.z + a.w * b.w;
}

__device__ __forceinline__ float red8(float p) {
    p += __shfl_xor_sync(FULL, p, 1);
    p += __shfl_xor_sync(FULL, p, 2);
    p += __shfl_xor_sync(FULL, p, 4);
    return p;
}

__global__ __launch_bounds__(256, 8) void edge_dot_kernel(
    const float* __restrict__ h,
    const int* __restrict__ src,
    const int* __restrict__ dst,
    float* __restrict__ out,
    int E)
{
    int gid = blockIdx.x * blockDim.x + threadIdx.x;
    int g = gid >> 3;                 // 8-lane group index
    int i = gid & 7;                  // lane within group
    long long e0 = (long long)g * EDGES_PER_GROUP;
    if (e0 >= E) return;

    if (e0 + EDGES_PER_GROUP <= E) {
        int4 s4 = *reinterpret_cast<const int4*>(src + e0);
        int4 d4 = *reinterpret_cast<const int4*>(dst + e0);

        // 8 independent gathers in flight
        float4 a0 = reinterpret_cast<const float4*>(h + (long long)s4.x * D)[i];
        float4 b0 = reinterpret_cast<const float4*>(h + (long long)d4.x * D)[i];
        float4 a1 = reinterpret_cast<const float4*>(h + (long long)s4.y * D)[i];
        float4 b1 = reinterpret_cast<const float4*>(h + (long long)d4.y * D)[i];
        float4 a2 = reinterpret_cast<const float4*>(h + (long long)s4.z * D)[i];
        float4 b2 = reinterpret_cast<const float4*>(h + (long long)d4.z * D)[i];
        float4 a3 = reinterpret_cast<const float4*>(h + (long long)s4.w * D)[i];
        float4 b3 = reinterpret_cast<const float4*>(h + (long long)d4.w * D)[i];

        float p0 = dot4(a0, b0);
        float p1 = dot4(a1, b1);
        float p2 = dot4(a2, b2);
        float p3 = dot4(a3, b3);

        // --- value-halving reduction over the 8-lane group (4 shuffles) ---
        bool hi4 = (i & 4) != 0;
        float ua = hi4 ? p0 : p2;
        float va = __shfl_xor_sync(FULL, ua, 4);
        float ub = hi4 ? p1 : p3;
        float vb = __shfl_xor_sync(FULL, ub, 4);
        float q0 = (hi4 ? p2 : p0) + va;
        float q1 = (hi4 ? p3 : p1) + vb;

        bool hi2 = (i & 2) != 0;
        float uc = hi2 ? q0 : q1;
        float vc = __shfl_xor_sync(FULL, uc, 2);
        float r = (hi2 ? q1 : q0) + vc;

        r += __shfl_xor_sync(FULL, r, 1);

        // lane 2k holds the full sum for edge e0+k (k = i>>1)
        if ((i & 1) == 0) out[e0 + (i >> 1)] = r;
    } else {
        // remainder (E not divisible by 4)
        for (long long e = e0; e < E; ++e) {
            int s = src[e];
            int d = dst[e];
            float4 a = reinterpret_cast<const float4*>(h + (long long)s * D)[i];
            float4 b = reinterpret_cast<const float4*>(h + (long long)d * D)[i];
            float p = red8(dot4(a, b));
            if (i == 0) out[e] = p;
        }
    }
}

extern "C" void kernel_launch(void* const* d_in, const int* in_sizes, int n_in,
                              void* d_out, int out_size)
{
    const float* h   = (const float*)d_in[0];
    const int*   src = (const int*)d_in[1];
    const int*   dst = (const int*)d_in[2];
    float*       out = (float*)d_out;

    int E = in_sizes[1];
    long long groups = ((long long)E + EDGES_PER_GROUP - 1) / EDGES_PER_GROUP;
    long long total_threads = groups * 8;
    int block = 256;
    int grid = (int)((total_threads + block - 1) / block);

    edge_dot_kernel<<<grid, block>>>(h, src, dst, out, E);
}